// round 4
// baseline (speedup 1.0000x reference)
#include <cuda_runtime.h>
#include <cstdint>

#define T_LEN 1024
#define S_LEN 1024
#define BSZ 4
#define EMB 1024
#define NH 16
#define HD 64
#define BH (BSZ*NH)   // 64

// ---------------- scratch (device globals; no allocations allowed) ----------
__device__ float g_q[BH * T_LEN * HD];              // [z=(b,h), t, d] scaled q
__device__ float g_k[BH * S_LEN * HD];              // [z, s, d]
__device__ float g_vt[BH * HD * S_LEN];             // [z, d, s]  (V transposed)
__device__ float g_ctx2[T_LEN * BSZ * EMB];         // [t, b, e]

// ============================================================================
__device__ __forceinline__ uint32_t f2tf32(float f) {
    uint32_t u;
    asm("cvt.rna.tf32.f32 %0, %1;" : "=r"(u) : "f"(f));
    return u;
}
__device__ __forceinline__ void mma16n8k8(float* c, const uint32_t* a, const uint32_t* b) {
    asm volatile(
        "mma.sync.aligned.m16n8k8.row.col.f32.tf32.tf32.f32 "
        "{%0,%1,%2,%3}, {%4,%5,%6,%7}, {%8,%9}, {%0,%1,%2,%3};"
        : "+f"(c[0]), "+f"(c[1]), "+f"(c[2]), "+f"(c[3])
        : "r"(a[0]), "r"(a[1]), "r"(a[2]), "r"(a[3]), "r"(b[0]), "r"(b[1]));
}

// ============================================================================
// Projection GEMM (tf32 mma.sync NT): C[m][n] = sum_k A[m*lda+k] * B[n*ldb+k]
// MODE 0: Q proj   -> g_q (bias, *0.125, [z,t,d] scatter)
// MODE 1: KV proj  -> g_k / g_vt (bias, scatter; V transposed)
// MODE 3: out proj -> Cout (+bias)
// ============================================================================
#define SROW 20

template<int TN, int MODE>
__global__ __launch_bounds__(256)
void gemm_mma(const float* __restrict__ Ain, int lda,
              const float* __restrict__ Bin, int ldb,
              const float* __restrict__ bias,
              float* __restrict__ Cout, int K)
{
    constexpr int FN = TN / 16;
    __shared__ uint32_t As[2][128 * SROW];
    __shared__ uint32_t Bs[2][TN * SROW];

    const int tid = threadIdx.x;
    const int wid = tid >> 5, lane = tid & 31;
    const int wm = wid & 3, wn = wid >> 2;
    const int g = lane >> 2, t4 = lane & 3;
    const int m0 = blockIdx.y * 128;
    const int n0 = blockIdx.x * TN;

    const float* A = (MODE == 3) ? g_ctx2 : Ain;
    const float* B = Bin;
    const int NI = K / 16;

    auto load_stage = [&](int s, int k0) {
        #pragma unroll
        for (int r = 0; r < 2; r++) {
            int f4 = tid + r * 256;
            int row = f4 >> 2, c4 = (f4 & 3) * 4;
            float4 v = *(const float4*)(A + (size_t)(m0 + row) * lda + k0 + c4);
            uint4 u = {f2tf32(v.x), f2tf32(v.y), f2tf32(v.z), f2tf32(v.w)};
            *(uint4*)&As[s][row * SROW + c4] = u;
        }
        #pragma unroll
        for (int r = 0; r < TN / 64; r++) {
            int f4 = tid + r * 256;
            int row = f4 >> 2, c4 = (f4 & 3) * 4;
            float4 v = *(const float4*)(B + (size_t)(n0 + row) * ldb + k0 + c4);
            uint4 u = {f2tf32(v.x), f2tf32(v.y), f2tf32(v.z), f2tf32(v.w)};
            *(uint4*)&Bs[s][row * SROW + c4] = u;
        }
    };

    float c[2][FN][4];
    #pragma unroll
    for (int mi = 0; mi < 2; mi++)
        #pragma unroll
        for (int ni = 0; ni < FN; ni++)
            #pragma unroll
            for (int e = 0; e < 4; e++) c[mi][ni][e] = 0.f;

    load_stage(0, 0);
    __syncthreads();

    for (int i = 0; i < NI; i++) {
        int s = i & 1;
        #pragma unroll
        for (int kk = 0; kk < 2; kk++) {
            uint32_t a[2][4], b[FN][2];
            #pragma unroll
            for (int mi = 0; mi < 2; mi++) {
                int r = wm * 32 + mi * 16 + g;
                int col = kk * 8 + t4;
                a[mi][0] = As[s][r * SROW + col];
                a[mi][1] = As[s][(r + 8) * SROW + col];
                a[mi][2] = As[s][r * SROW + col + 4];
                a[mi][3] = As[s][(r + 8) * SROW + col + 4];
            }
            #pragma unroll
            for (int ni = 0; ni < FN; ni++) {
                int rn = wn * (TN / 2) + ni * 8 + g;
                int col = kk * 8 + t4;
                b[ni][0] = Bs[s][rn * SROW + col];
                b[ni][1] = Bs[s][rn * SROW + col + 4];
            }
            #pragma unroll
            for (int mi = 0; mi < 2; mi++)
                #pragma unroll
                for (int ni = 0; ni < FN; ni++)
                    mma16n8k8(c[mi][ni], a[mi], b[ni]);
        }
        if (i + 1 < NI) {
            load_stage(s ^ 1, (i + 1) * 16);
            __syncthreads();
        }
    }

    #pragma unroll
    for (int mi = 0; mi < 2; mi++) {
        #pragma unroll
        for (int ni = 0; ni < FN; ni++) {
            #pragma unroll
            for (int e = 0; e < 4; e++) {
                int row = m0 + wm * 32 + mi * 16 + g + ((e >= 2) ? 8 : 0);
                int col = n0 + wn * (TN / 2) + ni * 8 + t4 * 2 + (e & 1);
                float v = c[mi][ni][e];
                if (MODE == 0) {
                    int t = row >> 2, b = row & 3;
                    int h = col >> 6, d = col & 63;
                    g_q[(size_t)(((b << 4) + h) * T_LEN + t) * HD + d] =
                        (v + bias[col]) * 0.125f;
                } else if (MODE == 1) {
                    v += bias[col];
                    int ff = col & 1023;
                    int h = ff >> 6, d = ff & 63;
                    int t = row >> 2, b = row & 3;
                    int zz = (b << 4) + h;
                    if (col < 1024)
                        g_k[(size_t)(zz * S_LEN + t) * HD + d] = v;
                    else
                        g_vt[(size_t)(zz * HD + d) * S_LEN + t] = v;
                } else {
                    Cout[(size_t)row * EMB + col] = v + bias[col];
                }
            }
        }
    }
}

// ============================================================================
// Fused attention: scores + softmax + mask + avg + PV, per (b, 32-row t-tile),
// looping all 16 heads. avg kept in registers (128/thread). No g_sc.
// smem: sc[32][1028] (131.6KB) | qb[32][68] | kv[128*68 / 64*132 overlay]
// ============================================================================
#define SC_STR 1028
#define SC_WORDS (32 * SC_STR)              // 32896
#define QB_WORDS (32 * 68)                  // 2176
#define KV_WORDS (128 * 68)                 // 8704 (>= 64*132 = 8448)
#define ATTN_SMEM_BYTES ((SC_WORDS + QB_WORDS + KV_WORDS) * 4)  // 175104

__global__ __launch_bounds__(256, 1)
void attn_fused(const float* __restrict__ mask, float* __restrict__ avg_out)
{
    extern __shared__ uint32_t sh[];
    uint32_t* sc = sh;                      // scores / probs tile
    uint32_t* qb = sh + SC_WORDS;           // Q tile (tf32)
    uint32_t* kv = qb + QB_WORDS;           // K or V chunk (tf32)

    const int tid = threadIdx.x;
    const int w = tid >> 5, lane = tid & 31;
    const int g = lane >> 2, t4 = lane & 3;
    const int t0 = blockIdx.x * 32;
    const int b  = blockIdx.y;

    // softmax/avg ownership: row r = tid>>3, cols c0+8j
    const int sr = tid >> 3;
    const int sc0 = tid & 7;
    const float* mrow = mask + ((size_t)(b * T_LEN + t0 + sr)) * S_LEN;

    float avg[128];
    #pragma unroll
    for (int j = 0; j < 128; j++) avg[j] = 0.f;

    for (int h = 0; h < NH; h++) {
        const int z = (b << 4) + h;
        const float* Qz = g_q + (size_t)z * (T_LEN * HD);
        const float* Kz = g_k + (size_t)z * (S_LEN * HD);
        const float* Vz = g_vt + (size_t)z * (HD * S_LEN);

        __syncthreads();   // prior head done with qb/sc

        // ---- load Q tile 32x64 -> qb (tf32), stride 68
        #pragma unroll
        for (int r = 0; r < 2; r++) {
            int f4 = tid + r * 256;         // 0..511
            int row = f4 >> 4, c4 = (f4 & 15) * 4;
            float4 v = *(const float4*)(Qz + (size_t)(t0 + row) * HD + c4);
            uint4 u = {f2tf32(v.x), f2tf32(v.y), f2tf32(v.z), f2tf32(v.w)};
            *(uint4*)&qb[row * 68 + c4] = u;
        }

        // ---- scores: 8 chunks of 128 s-cols
        for (int ch = 0; ch < 8; ch++) {
            int s0 = ch * 128;
            __syncthreads();  // kv free & (first iter) qb ready
            #pragma unroll
            for (int r = 0; r < 8; r++) {
                int f4 = tid + r * 256;     // 0..2047
                int row = f4 >> 4, c4 = (f4 & 15) * 4;
                float4 v = *(const float4*)(Kz + (size_t)(s0 + row) * HD + c4);
                uint4 u = {f2tf32(v.x), f2tf32(v.y), f2tf32(v.z), f2tf32(v.w)};
                *(uint4*)&kv[row * 68 + c4] = u;
            }
            __syncthreads();

            float c[2][2][4];
            #pragma unroll
            for (int mi = 0; mi < 2; mi++)
                #pragma unroll
                for (int ni = 0; ni < 2; ni++)
                    #pragma unroll
                    for (int e = 0; e < 4; e++) c[mi][ni][e] = 0.f;

            #pragma unroll
            for (int kk = 0; kk < 8; kk++) {
                uint32_t a[2][4], bb[2][2];
                int col = kk * 8 + t4;
                #pragma unroll
                for (int mi = 0; mi < 2; mi++) {
                    int r = mi * 16 + g;
                    a[mi][0] = qb[r * 68 + col];
                    a[mi][1] = qb[(r + 8) * 68 + col];
                    a[mi][2] = qb[r * 68 + col + 4];
                    a[mi][3] = qb[(r + 8) * 68 + col + 4];
                }
                #pragma unroll
                for (int ni = 0; ni < 2; ni++) {
                    int rn = w * 16 + ni * 8 + g;
                    bb[ni][0] = kv[rn * 68 + col];
                    bb[ni][1] = kv[rn * 68 + col + 4];
                }
                #pragma unroll
                for (int mi = 0; mi < 2; mi++)
                    #pragma unroll
                    for (int ni = 0; ni < 2; ni++)
                        mma16n8k8(c[mi][ni], a[mi], bb[ni]);
            }
            // write scores (f32) to sc
            #pragma unroll
            for (int mi = 0; mi < 2; mi++)
                #pragma unroll
                for (int ni = 0; ni < 2; ni++)
                    #pragma unroll
                    for (int e = 0; e < 4; e++) {
                        int row = mi * 16 + g + ((e >= 2) ? 8 : 0);
                        int col = s0 + w * 16 + ni * 8 + t4 * 2 + (e & 1);
                        sc[row * SC_STR + col] = __float_as_uint(c[mi][ni][e]);
                    }
        }
        __syncthreads();

        // ---- softmax + mask + avg (thread owns row sr, cols sc0+8j)
        {
            uint32_t* rowp = sc + sr * SC_STR;
            float mx = -1e30f;
            #pragma unroll
            for (int j = 0; j < 128; j++)
                mx = fmaxf(mx, __uint_as_float(rowp[sc0 + 8 * j]));
            #pragma unroll
            for (int o = 4; o >= 1; o >>= 1)
                mx = fmaxf(mx, __shfl_xor_sync(0xffffffffu, mx, o));

            float sum = 0.f;
            #pragma unroll
            for (int j = 0; j < 128; j++) {
                float x = __expf(__uint_as_float(rowp[sc0 + 8 * j]) - mx);
                rowp[sc0 + 8 * j] = __float_as_uint(x);
                sum += x;
            }
            #pragma unroll
            for (int o = 4; o >= 1; o >>= 1)
                sum += __shfl_xor_sync(0xffffffffu, sum, o);
            float inv = 1.f / sum;

            #pragma unroll
            for (int j = 0; j < 128; j++) {
                int col = sc0 + 8 * j;
                float p = __uint_as_float(rowp[col]) * inv * mrow[col];
                avg[j] += p;
                rowp[col] = f2tf32(p);
            }
        }

        // ---- PV: ctx[32][64] += P[32][1024] * Vt[64][1024]^T, 8 s-chunks
        float cc[2][4];
        #pragma unroll
        for (int mi = 0; mi < 2; mi++)
            #pragma unroll
            for (int e = 0; e < 4; e++) cc[mi][e] = 0.f;

        for (int ch = 0; ch < 8; ch++) {
            int s0 = ch * 128;
            __syncthreads();  // sc probs visible (first) / kv free
            #pragma unroll
            for (int r = 0; r < 8; r++) {
                int f4 = tid + r * 256;     // 0..2047
                int row = f4 >> 5, c4 = (f4 & 31) * 4;
                float4 v = *(const float4*)(Vz + (size_t)row * S_LEN + s0 + c4);
                uint4 u = {f2tf32(v.x), f2tf32(v.y), f2tf32(v.z), f2tf32(v.w)};
                *(uint4*)&kv[row * 132 + c4] = u;
            }
            __syncthreads();

            #pragma unroll
            for (int kk = 0; kk < 16; kk++) {
                uint32_t a[2][4], bb[2];
                int col = kk * 8 + t4;
                #pragma unroll
                for (int mi = 0; mi < 2; mi++) {
                    int r = mi * 16 + g;
                    a[mi][0] = sc[r * SC_STR + s0 + col];
                    a[mi][1] = sc[(r + 8) * SC_STR + s0 + col];
                    a[mi][2] = sc[r * SC_STR + s0 + col + 4];
                    a[mi][3] = sc[(r + 8) * SC_STR + s0 + col + 4];
                }
                int rn = w * 8 + g;
                bb[0] = kv[rn * 132 + col];
                bb[1] = kv[rn * 132 + col + 4];
                #pragma unroll
                for (int mi = 0; mi < 2; mi++)
                    mma16n8k8(cc[mi], a[mi], bb);
            }
        }

        // ---- write ctx directly into [t,b,e] layout
        #pragma unroll
        for (int mi = 0; mi < 2; mi++)
            #pragma unroll
            for (int e = 0; e < 4; e++) {
                int row = mi * 16 + g + ((e >= 2) ? 8 : 0);
                int d = w * 8 + t4 * 2 + (e & 1);
                g_ctx2[(size_t)((t0 + row) * BSZ + b) * EMB + h * HD + d] = cc[mi][e];
            }
    }

    // ---- write avg (sum over heads / 16)
    {
        float* arow = avg_out + ((size_t)(b * T_LEN + t0 + sr)) * S_LEN;
        #pragma unroll
        for (int j = 0; j < 128; j++)
            arow[sc0 + 8 * j] = avg[j] * (1.0f / NH);
    }
}

// ---------------------------------------------------------------------------
extern "C" void kernel_launch(void* const* d_in, const int* in_sizes, int n_in,
                              void* d_out, int out_size)
{
    const float* query = (const float*)d_in[0];
    const float* key   = (const float*)d_in[1];
    const float* mask  = (const float*)d_in[2];
    const float* w_in  = (const float*)d_in[3];
    const float* b_in  = (const float*)d_in[4];
    const float* w_out = (const float*)d_in[5];
    const float* b_out = (const float*)d_in[6];
    float* out = (float*)d_out;                         // [t][b][e]
    float* avg = out + (size_t)T_LEN * BSZ * EMB;       // [b][t][s]

    cudaFuncSetAttribute(attn_fused, cudaFuncAttributeMaxDynamicSharedMemorySize,
                         ATTN_SMEM_BYTES);

    dim3 blk(256);
    // 1) Q projection
    gemm_mma<128, 0><<<dim3(8, 32, 1), blk>>>(query, EMB, w_in, EMB, b_in, nullptr, EMB);
    // 2) KV projection
    gemm_mma<128, 1><<<dim3(16, 32, 1), blk>>>(key, EMB, w_in + EMB * EMB, EMB,
                                               b_in + EMB, nullptr, EMB);
    // 3) fused attention (scores+softmax+mask+avg+PV) -> g_ctx2, avg
    attn_fused<<<dim3(32, 4), blk, ATTN_SMEM_BYTES>>>(mask, avg);
    // 4) output projection -> d_out
    gemm_mma<128, 3><<<dim3(8, 32, 1), blk>>>(nullptr, EMB, w_out, EMB, b_out, out, EMB);
}